// round 9
// baseline (speedup 1.0000x reference)
#include <cuda_runtime.h>
#include <math.h>

#define TS   64
#define BB   32
#define VV   32000
#define HH   1024
#define EMBD 512
#define G4   4096
#define HB   32768          // HH*BB

typedef unsigned long long ull;

// ---------------- device scratch ----------------
__device__ float d_emb[(size_t)TS * EMBD * BB];   // [t][k][b]
__device__ float d_comb[2 * HB];
__device__ float d_h0p[HB];
__device__ float d_h1i[HB];
__device__ float d_c0p[HB], d_c1p[HB];
__device__ float d_g[4 * (size_t)G4 * BB];
__device__ float d_kp[8 * (size_t)HB];
__device__ float d_cp[8 * (size_t)HB];
__device__ float d_hbuf[(size_t)TS * HB];
__device__ float d_keys[(size_t)TS * HB];
__device__ float d_sc[TS * BB];
__device__ float d_dist[2 * TS * BB];
__device__ float d_sumv[HB];
__device__ float d_pexp[(size_t)VV * BB];
__device__ float d_red[500 * BB];
__device__ float d_ce[BB], d_f[BB], d_cw[BB];

// tile-major packed weights: tile(jt,kt) = 32k x 64j contiguous (2048 floats)
__device__ float dP_ih0[(size_t)1536 * G4];
__device__ float dP_hh0[(size_t)HH * G4];
__device__ float dP_ih1[(size_t)HH * G4];
__device__ float dP_hh1[(size_t)HH * G4];
__device__ float dP_k[(size_t)HH * HH];
__device__ float dP_c[(size_t)2048 * HH];
__device__ float dP_p[(size_t)HH * VV];

__device__ __forceinline__ float sigm(float x) { return 1.f / (1.f + expf(-x)); }

__device__ __forceinline__ void ffma2(ull& d, ull a, ull x) {
    asm("fma.rn.f32x2 %0, %1, %2, %0;" : "+l"(d) : "l"(a), "l"(x));
}
__device__ __forceinline__ ull pack2(float x) {
    ull r; unsigned int xi = __float_as_uint(x);
    asm("mov.b64 %0, {%1, %1};" : "=l"(r) : "r"(xi));
    return r;
}
__device__ __forceinline__ void unpack2(ull v, float& lo, float& hi) {
    unsigned int a, b;
    asm("mov.b64 {%0, %1}, %2;" : "=r"(a), "=r"(b) : "l"(v));
    lo = __uint_as_float(a); hi = __uint_as_float(b);
}
__device__ __forceinline__ unsigned smem_u32(const void* p) {
    return (unsigned)__cvta_generic_to_shared(p);
}
__device__ __forceinline__ void mbar_init(unsigned mba) {
    asm volatile("mbarrier.init.shared.b64 [%0], 1;" :: "r"(mba) : "memory");
}
__device__ __forceinline__ void mbar_expect(unsigned mba, unsigned bytes) {
    asm volatile("mbarrier.arrive.expect_tx.shared.b64 _, [%0], %1;"
                 :: "r"(mba), "r"(bytes) : "memory");
}
__device__ __forceinline__ void bulk_cp(unsigned sdst, const void* gsrc,
                                        unsigned bytes, unsigned mba) {
    asm volatile("cp.async.bulk.shared::cluster.global.mbarrier::complete_tx::bytes "
                 "[%0], [%1], %2, [%3];"
                 :: "r"(sdst), "l"(gsrc), "r"(bytes), "r"(mba) : "memory");
}
__device__ __forceinline__ void mwait(unsigned mba, int ph) {
    asm volatile(
        "{\n\t.reg .pred P;\n"
        "W%=:\n\t"
        "mbarrier.try_wait.parity.acquire.cta.shared::cta.b64 P, [%0], %1, 0x989680;\n\t"
        "@P bra D%=;\n\t"
        "bra W%=;\n"
        "D%=:\n\t}"
        :: "r"(mba), "r"(ph) : "memory");
}

// ---------------- repack: row-major [J][K] -> tile-major 32k x 64j ----------
struct TransTab { const float* s[7]; float* d[7]; int J[7]; int K[7]; };

__global__ void __launch_bounds__(256) k_trans(TransTab tt)
{
    __shared__ float sm[32][65];
    int id = blockIdx.x;
    int m = 0;
    for (;;) {
        int n = (tt.J[m] >> 6) * (tt.K[m] >> 5);
        if (id < n) break;
        id -= n; m++;
    }
    const float* src = tt.s[m];
    float* dst = tt.d[m];
    int J = tt.J[m], K = tt.K[m];
    int jtn = J >> 6;
    int jt = id % jtn, kt = id / jtn;
    int j0 = jt << 6, k0 = kt << 5;
    int tid = threadIdx.x;
#pragma unroll
    for (int i = 0; i < 2; i++) {
        int idx = tid + 256 * i;
        int jj = idx >> 3, q = (idx & 7) << 2;
        float4 v = *(const float4*)(src + (size_t)(j0 + jj) * K + k0 + q);
        sm[q + 0][jj] = v.x; sm[q + 1][jj] = v.y;
        sm[q + 2][jj] = v.z; sm[q + 3][jj] = v.w;
    }
    __syncthreads();
    float* base = dst + ((size_t)jt * (K >> 5) + kt) * 2048;
#pragma unroll
    for (int i = 0; i < 2; i++) {
        int idx = tid + 256 * i;
        int kk = idx >> 4, j4 = (idx & 15) << 2;
        *(float4*)(base + kk * 64 + j4) =
            make_float4(sm[kk][j4], sm[kk][j4 + 1], sm[kk][j4 + 2], sm[kk][j4 + 3]);
    }
}

// ---------------- GEMM: tile-major A, cp.async.bulk 3-stage mbarrier ring ----
// JT=64 rows/block. k-split over gridDim.y; out plane per split (split 0 +bias).
__global__ void __launch_bounds__(256) k_gemm(
    const float* __restrict__ P0, const float* __restrict__ X0, int ldt0, int kto0, int t0,
    const float* __restrict__ P1, const float* __restrict__ X1, int ldt1, int kto1, int t1,
    const float* __restrict__ P2, const float* __restrict__ X2, int ldt2, int kto2, int t2,
    int tps, const float* __restrict__ bias1, const float* __restrict__ bias2,
    float* __restrict__ out, long long outPlane)
{
    __shared__ __align__(16) float As[3][2048];
    __shared__ __align__(16) float Xs[3][1024];
    __shared__ __align__(8)  ull  mbar[3];

    const int tid = threadIdx.x;
    const int b   = tid & 31, rg = tid >> 5;
    const int jt  = blockIdx.x;
    const int total = t0 + t1 + t2;
    const int g0 = blockIdx.y * tps;
    const int g1 = min(total, g0 + tps);

    const unsigned mb  = smem_u32(mbar);
    const unsigned sAs = smem_u32(As);
    const unsigned sXs = smem_u32(Xs);

    if (tid == 0) {
        mbar_init(mb); mbar_init(mb + 8); mbar_init(mb + 16);
        asm volatile("fence.proxy.async.shared::cta;" ::: "memory");
    }
    __syncthreads();

    auto issue = [&](int g, int st) {
        const float* P; const float* X; int ldt, kto, lk;
        if (g < t0)           { P = P0; X = X0; ldt = ldt0; kto = kto0; lk = g; }
        else if (g < t0 + t1) { P = P1; X = X1; ldt = ldt1; kto = kto1; lk = g - t0; }
        else                  { P = P2; X = X2; ldt = ldt2; kto = kto2; lk = g - t0 - t1; }
        const float* a = P + ((size_t)jt * ldt + kto + lk) * 2048;
        const float* x = X + (size_t)lk * 1024;
        unsigned mba = mb + st * 8;
        mbar_expect(mba, 8192 + 4096);
        bulk_cp(sAs + st * 8192, a, 8192, mba);
        bulk_cp(sXs + st * 4096, x, 4096, mba);
    };

    if (tid == 0)
        for (int i = 0; i < 2 && g0 + i < g1; i++) issue(g0 + i, i);

    ull acc[4] = {0ull, 0ull, 0ull, 0ull};
    int st = 0, ph = 0;
    for (int g = g0; g < g1; g++) {
        mwait(mb + st * 8, ph);
        __syncthreads();
        if (tid == 0 && g + 2 < g1) {
            int rs = st + 2; if (rs >= 3) rs -= 3;
            issue(g + 2, rs);
        }
        const float* A_ = As[st];
        const float* X_ = Xs[st];
#pragma unroll
        for (int kk = 0; kk < 32; kk++) {
            ull xp = pack2(X_[kk * 32 + b]);
            const float* ab = A_ + kk * 64 + rg * 8;
            ulonglong2 u0 = *(const ulonglong2*)(ab);
            ulonglong2 u1 = *(const ulonglong2*)(ab + 4);
            ffma2(acc[0], u0.x, xp);
            ffma2(acc[1], u0.y, xp);
            ffma2(acc[2], u1.x, xp);
            ffma2(acc[3], u1.y, xp);
        }
        if (++st == 3) { st = 0; ph ^= 1; }
    }

    float* outp = out + blockIdx.y * outPlane;
#pragma unroll
    for (int p = 0; p < 4; p++) {
        float lo, hi;
        unpack2(acc[p], lo, hi);
        const int j = jt * 64 + rg * 8 + 2 * p;
        if (blockIdx.y == 0) {
            if (bias1) { lo += bias1[j]; hi += bias1[j + 1]; }
            if (bias2) { lo += bias2[j]; hi += bias2[j + 1]; }
        }
        outp[(size_t)j * BB + b]       = lo;
        outp[(size_t)(j + 1) * BB + b] = hi;
    }
}

// ---------------- logits: same pipeline + exp epilogue + block sum ----------
__global__ void __launch_bounds__(256) k_logits(
    const float* __restrict__ Pp, const float* __restrict__ comb,
    const float* __restrict__ bp, float* __restrict__ pexp, float* __restrict__ red)
{
    __shared__ __align__(16) float As[3][2048];
    __shared__ __align__(16) float Xs[3][1024];
    __shared__ __align__(8)  ull  mbar[3];
    __shared__ float sr[8][33];

    const int tid = threadIdx.x;
    const int b   = tid & 31, rg = tid >> 5;
    const int jt  = blockIdx.x;

    const unsigned mb  = smem_u32(mbar);
    const unsigned sAs = smem_u32(As);
    const unsigned sXs = smem_u32(Xs);

    if (tid == 0) {
        mbar_init(mb); mbar_init(mb + 8); mbar_init(mb + 16);
        asm volatile("fence.proxy.async.shared::cta;" ::: "memory");
    }
    __syncthreads();

    auto issue = [&](int g, int st) {
        const float* a = Pp + ((size_t)jt * 32 + g) * 2048;
        const float* x = comb + (size_t)g * 1024;
        unsigned mba = mb + st * 8;
        mbar_expect(mba, 8192 + 4096);
        bulk_cp(sAs + st * 8192, a, 8192, mba);
        bulk_cp(sXs + st * 4096, x, 4096, mba);
    };

    if (tid == 0) { issue(0, 0); issue(1, 1); }

    ull acc[4] = {0ull, 0ull, 0ull, 0ull};
    int st = 0, ph = 0;
    for (int g = 0; g < 32; g++) {
        mwait(mb + st * 8, ph);
        __syncthreads();
        if (tid == 0 && g + 2 < 32) {
            int rs = st + 2; if (rs >= 3) rs -= 3;
            issue(g + 2, rs);
        }
        const float* A_ = As[st];
        const float* X_ = Xs[st];
#pragma unroll
        for (int kk = 0; kk < 32; kk++) {
            ull xp = pack2(X_[kk * 32 + b]);
            const float* ab = A_ + kk * 64 + rg * 8;
            ulonglong2 u0 = *(const ulonglong2*)(ab);
            ulonglong2 u1 = *(const ulonglong2*)(ab + 4);
            ffma2(acc[0], u0.x, xp);
            ffma2(acc[1], u0.y, xp);
            ffma2(acc[2], u1.x, xp);
            ffma2(acc[3], u1.y, xp);
        }
        if (++st == 3) { st = 0; ph ^= 1; }
    }

    float psum = 0.f;
#pragma unroll
    for (int p = 0; p < 4; p++) {
        float lo, hi; unpack2(acc[p], lo, hi);
        int j = jt * 64 + rg * 8 + 2 * p;
        float e0 = expf(lo + bp[j]);
        float e1 = expf(hi + bp[j + 1]);
        pexp[(size_t)j * BB + b]       = e0;
        pexp[(size_t)(j + 1) * BB + b] = e1;
        psum += e0 + e1;
    }
    sr[rg][b] = psum;
    __syncthreads();
    if (tid < 32) {
        float v = 0.f;
#pragma unroll
        for (int r = 0; r < 8; r++) v += sr[r][tid];
        red[jt * BB + tid] = v;
    }
}

// ---------------- small kernels (unchanged shapes) ----------------
__global__ void k_embed_all(const float* __restrict__ E, const int* __restrict__ toks,
                            float* __restrict__ emb)
{
    int i = blockIdx.x * 256 + threadIdx.x;
    int b = i & 31, k = (i >> 5) & (EMBD - 1), t = i >> 14;
    emb[i] = E[(size_t)toks[t * BB + b] * EMBD + k];
}

__global__ void k_init(const float* __restrict__ h0, const float* __restrict__ c0,
                       float* h0p, float* h1i, float* c0p, float* c1p, float* comb)
{
    int i = blockIdx.x * 256 + threadIdx.x;
    int h = i >> 5, b = i & 31;
    h0p[i]  = h0[(size_t)b * HH + h];
    h1i[i]  = h0[(size_t)(BB + b) * HH + h];
    c0p[i]  = c0[(size_t)b * HH + h];
    c1p[i]  = c0[(size_t)(BB + b) * HH + h];
    comb[i] = 0.f;
    comb[HB + i] = 0.f;
}

__global__ void k_gates(const float* __restrict__ gp, float* __restrict__ c,
                        float* __restrict__ hout)
{
    int i = blockIdx.x * 256 + threadIdx.x;
    float g[4];
#pragma unroll
    for (int m = 0; m < 4; m++) {
        size_t o = (size_t)m * HB + i;
        g[m] = gp[o] + gp[(size_t)G4 * BB + o] + gp[2 * (size_t)G4 * BB + o]
             + gp[3 * (size_t)G4 * BB + o];
    }
    float c2 = sigm(g[1]) * c[i] + sigm(g[0]) * tanhf(g[2]);
    c[i] = c2;
    hout[i] = sigm(g[3]) * tanhf(c2);
}

__global__ void __launch_bounds__(256) k_scores(float* __restrict__ keys,
        const float* __restrict__ kp, const float* __restrict__ htop,
        const int* __restrict__ toks, float* __restrict__ sc, int t)
{
    int s = blockIdx.x;
    int lane = threadIdx.x & 31, w = threadIdx.x >> 5;
    float acc = 0.f;
    if (s == t) {
        float* kf = keys + (size_t)t * HB;
        for (int h = w; h < HH; h += 8) {
            int i = h * BB + lane;
            float v = 0.f;
#pragma unroll
            for (int p = 0; p < 8; p++) v += kp[(size_t)p * HB + i];
            kf[i] = v;
            acc = fmaf(v, htop[i], acc);
        }
    } else {
        const float* ks = keys + (size_t)s * HB;
        for (int h = w; h < HH; h += 8)
            acc = fmaf(ks[h * BB + lane], htop[h * BB + lane], acc);
    }
    __shared__ float red[8][BB];
    red[w][lane] = acc;
    __syncthreads();
    if (w == 0) {
        float v = acc;
#pragma unroll
        for (int r = 1; r < 8; r++) v += red[r][lane];
        if (toks[s * BB + lane] == 0) v -= 99999.f;
        sc[s * BB + lane] = v;
    }
}

__global__ void k_summary(const float* __restrict__ sc, const float* __restrict__ hbuf,
                          int t, float* __restrict__ dist, float* __restrict__ sum)
{
    __shared__ float sd[TS * BB];
    int tid = threadIdx.x;
    if (tid < 32) {
        int b = tid;
        float m = -1e30f;
        for (int s = 0; s <= t; s++) m = fmaxf(m, sc[s * BB + b]);
        float ss = 0.f;
        for (int s = 0; s <= t; s++) {
            float e = expf(sc[s * BB + b] - m);
            sd[s * BB + b] = e;
            ss += e;
        }
        float inv = 1.f / ss;
        for (int s = 0; s <= t; s++) {
            float dv = sd[s * BB + b] * inv;
            sd[s * BB + b] = dv;
            if (blockIdx.x == 0) dist[s * BB + b] = dv;
        }
    }
    __syncthreads();
    int gi = blockIdx.x * 256 + tid;
    int b = gi & 31;
    float acc = 0.f;
    for (int s = 0; s <= t; s++)
        acc = fmaf(sd[s * BB + b], hbuf[(size_t)s * HB + gi], acc);
    sum[gi] = acc;
}

__global__ void k_fincomb(const float* __restrict__ cp, float* __restrict__ comb)
{
    int i = blockIdx.x * 256 + threadIdx.x;
    float v = 0.f;
#pragma unroll
    for (int p = 0; p < 8; p++) v += cp[(size_t)p * HB + i];
    comb[i] = v;
}

__global__ void k_reduce2(const float* __restrict__ red, const float* __restrict__ pexp,
                          float* __restrict__ ce, float* __restrict__ f,
                          float* __restrict__ cw)
{
    int b = threadIdx.x;
    float S = 0.f;
    for (int i = 0; i < 500; i++) S += red[i * BB + b];
    float inv = 1.f / S;
    float c = pexp[3 * BB + b] * inv;
    ce[b] = c * 1e-7f;
    f[b]  = (1.f - c) * inv;
    cw[b] = c;
}

__global__ void __launch_bounds__(256) k_out(const float* __restrict__ pexp,
        const float* __restrict__ ce, const float* __restrict__ f,
        const float* __restrict__ cw, const int* __restrict__ toks,
        const float* __restrict__ dist, float* __restrict__ out, int t)
{
    __shared__ float tile[128 * 33];
    int v0 = blockIdx.x * 128;
    int lane = threadIdx.x & 31, w = threadIdx.x >> 5;
    float ceL = ce[lane], fL = f[lane];
#pragma unroll
    for (int k = 0; k < 16; k++) {
        int vr = (k << 3) + w;
        tile[vr * 33 + lane] = logf(ceL + fL * pexp[(size_t)(v0 + vr) * BB + lane]);
    }
    __syncthreads();
    int bo = threadIdx.x >> 3, q = threadIdx.x & 7;
    float* op = out + (size_t)(t * BB + bo) * VV + v0;
#pragma unroll
    for (int i = 0; i < 4; i++) {
        int vb = (q + (i << 3)) << 2;
        *(float4*)(op + vb) = make_float4(tile[vb * 33 + bo],
                                          tile[(vb + 1) * 33 + bo],
                                          tile[(vb + 2) * 33 + bo],
                                          tile[(vb + 3) * 33 + bo]);
    }
    __syncthreads();
    float cwL = cw[lane];
    for (int s = w; s <= t; s += 8) {
        int v = toks[s * BB + lane];
        if (v >= v0 && v < v0 + 128) {
            bool first = true;
            for (int sp = 0; sp < s; sp++)
                if (toks[sp * BB + lane] == v) { first = false; break; }
            if (first) {
                float S = 0.f;
                for (int sp = s; sp <= t; sp++)
                    if (toks[sp * BB + lane] == v) S += dist[sp * BB + lane];
                out[(size_t)(t * BB + lane) * VV + v] =
                    logf(ceL + cwL * S + fL * pexp[(size_t)v * BB + lane]);
            }
        }
    }
}

// ---------------- host ----------------
extern "C" void kernel_launch(void* const* d_in, const int* in_sizes, int n_in,
                              void* d_out, int out_size)
{
    const int*   toks = (const int*)d_in[0];
    const float* h0   = (const float*)d_in[1];
    const float* c0   = (const float*)d_in[2];
    const float* E    = (const float*)d_in[3];
    const float* Wih0 = (const float*)d_in[4];
    const float* Whh0 = (const float*)d_in[5];
    const float* bih0 = (const float*)d_in[6];
    const float* bhh0 = (const float*)d_in[7];
    const float* Wih1 = (const float*)d_in[8];
    const float* Whh1 = (const float*)d_in[9];
    const float* bih1 = (const float*)d_in[10];
    const float* bhh1 = (const float*)d_in[11];
    const float* Wk   = (const float*)d_in[12];
    const float* bk   = (const float*)d_in[13];
    const float* Wc   = (const float*)d_in[14];
    const float* bc   = (const float*)d_in[15];
    const float* Wp   = (const float*)d_in[16];
    const float* bp   = (const float*)d_in[17];
    float* out = (float*)d_out;

    float *emb, *comb, *h0p, *h1i, *c0p, *c1p, *g, *kp, *cp, *hbuf, *keys;
    float *sc, *dist, *sumv, *pexp, *red, *ce, *f, *cw;
    float *Pih0, *Phh0, *Pih1, *Phh1, *Pk, *Pc, *Pp;
    cudaGetSymbolAddress((void**)&emb,  d_emb);
    cudaGetSymbolAddress((void**)&comb, d_comb);
    cudaGetSymbolAddress((void**)&h0p,  d_h0p);
    cudaGetSymbolAddress((void**)&h1i,  d_h1i);
    cudaGetSymbolAddress((void**)&c0p,  d_c0p);
    cudaGetSymbolAddress((void**)&c1p,  d_c1p);
    cudaGetSymbolAddress((void**)&g,    d_g);
    cudaGetSymbolAddress((void**)&kp,   d_kp);
    cudaGetSymbolAddress((void**)&cp,   d_cp);
    cudaGetSymbolAddress((void**)&hbuf, d_hbuf);
    cudaGetSymbolAddress((void**)&keys, d_keys);
    cudaGetSymbolAddress((void**)&sc,   d_sc);
    cudaGetSymbolAddress((void**)&dist, d_dist);
    cudaGetSymbolAddress((void**)&sumv, d_sumv);
    cudaGetSymbolAddress((void**)&pexp, d_pexp);
    cudaGetSymbolAddress((void**)&red,  d_red);
    cudaGetSymbolAddress((void**)&ce,   d_ce);
    cudaGetSymbolAddress((void**)&f,    d_f);
    cudaGetSymbolAddress((void**)&cw,   d_cw);
    cudaGetSymbolAddress((void**)&Pih0, dP_ih0);
    cudaGetSymbolAddress((void**)&Phh0, dP_hh0);
    cudaGetSymbolAddress((void**)&Pih1, dP_ih1);
    cudaGetSymbolAddress((void**)&Phh1, dP_hh1);
    cudaGetSymbolAddress((void**)&Pk,   dP_k);
    cudaGetSymbolAddress((void**)&Pc,   dP_c);
    cudaGetSymbolAddress((void**)&Pp,   dP_p);

    static cudaStream_t sA = nullptr;
    static cudaEvent_t evC[2], evD[2];
    if (!sA) {
        cudaStreamCreateWithFlags(&sA, cudaStreamNonBlocking);
        for (int i = 0; i < 2; i++) {
            cudaEventCreateWithFlags(&evC[i], cudaEventDisableTiming);
            cudaEventCreateWithFlags(&evD[i], cudaEventDisableTiming);
        }
    }

    const long long GP = (long long)G4 * BB;

    k_embed_all<<<(TS * EMBD * BB) / 256, 256>>>(E, toks, emb);
    k_init<<<HB / 256, 256>>>(h0, c0, h0p, h1i, c0p, c1p, comb);

    TransTab tt;
    tt.s[0] = Wih0; tt.d[0] = Pih0; tt.J[0] = G4;   tt.K[0] = 1536;
    tt.s[1] = Whh0; tt.d[1] = Phh0; tt.J[1] = G4;   tt.K[1] = HH;
    tt.s[2] = Wih1; tt.d[2] = Pih1; tt.J[2] = G4;   tt.K[2] = HH;
    tt.s[3] = Whh1; tt.d[3] = Phh1; tt.J[3] = G4;   tt.K[3] = HH;
    tt.s[4] = Wk;   tt.d[4] = Pk;   tt.J[4] = HH;   tt.K[4] = HH;
    tt.s[5] = Wc;   tt.d[5] = Pc;   tt.J[5] = HH;   tt.K[5] = 2048;
    tt.s[6] = Wp;   tt.d[6] = Pp;   tt.J[6] = VV;   tt.K[6] = HH;
    int ntiles = 0;
    for (int m = 0; m < 7; m++) ntiles += (tt.J[m] >> 6) * (tt.K[m] >> 5);
    k_trans<<<ntiles, 256>>>(tt);

    for (int t = 0; t < TS; t++) {
        float* htop = hbuf + (size_t)t * HB;
        const float* h1prev   = t ? hbuf + (size_t)(t - 1) * HB : h1i;
        const float* emb_t    = emb + (size_t)t * EMBD * BB;
        const float* combPrev = comb + (size_t)((t + 1) & 1) * HB;
        float*       combCur  = comb + (size_t)(t & 1) * HB;
        float*       distCur  = dist + (size_t)(t & 1) * TS * BB;

        if (t >= 2) cudaStreamWaitEvent(0, evD[t & 1], 0);

        // LSTM0: 80 tiles (emb 16 | comb 32 | h0 32), ksplit 4 x 20
        k_gemm<<<dim3(G4 / 64, 4), 256>>>(
            Pih0, emb_t,    48, 0,  16,
            Pih0, combPrev, 48, 16, 32,
            Phh0, h0p,      32, 0,  32,
            20, bih0, bhh0, g, GP);
        k_gates<<<HB / 256, 256>>>(g, c0p, h0p);

        // LSTM1: 64 tiles, ksplit 4 x 16
        k_gemm<<<dim3(G4 / 64, 4), 256>>>(
            Pih1, h0p,    32, 0, 32,
            Phh1, h1prev, 32, 0, 32,
            nullptr, nullptr, 0, 0, 0,
            16, bih1, bhh1, g, GP);
        k_gates<<<HB / 256, 256>>>(g, c1p, htop);

        // keys[t]: 32 tiles, ksplit 8 x 4
        k_gemm<<<dim3(HH / 64, 8), 256>>>(
            Pk, htop, 32, 0, 32,
            nullptr, nullptr, 0, 0, 0,
            nullptr, nullptr, 0, 0, 0,
            4, bk, nullptr, kp, (long long)HB);
        k_scores<<<t + 1, 256>>>(keys, kp, htop, toks, sc, t);
        k_summary<<<HB / 256, 256>>>(sc, hbuf, t, distCur, sumv);

        // comb: 64 tiles (htop 32 | sumv 32), ksplit 8 x 8
        k_gemm<<<dim3(HH / 64, 8), 256>>>(
            Pc, htop, 64, 0,  32,
            Pc, sumv, 64, 32, 32,
            nullptr, nullptr, 0, 0, 0,
            8, bc, nullptr, cp, (long long)HB);
        k_fincomb<<<HB / 256, 256>>>(cp, combCur);
        cudaEventRecord(evC[t & 1], 0);

        // side chain (stream A)
        cudaStreamWaitEvent(sA, evC[t & 1], 0);
        k_logits<<<VV / 64, 256, 0, sA>>>(Pp, combCur, bp, pexp, red);
        k_reduce2<<<1, 32, 0, sA>>>(red, pexp, ce, f, cw);
        k_out<<<VV / 128, 256, 0, sA>>>(pexp, ce, f, cw, toks, distCur, out, t);
        cudaEventRecord(evD[t & 1], sA);
    }

    cudaStreamWaitEvent(0, evD[(TS - 1) & 1], 0);
    cudaStreamWaitEvent(0, evD[TS & 1], 0);
}

// round 12
// speedup vs baseline: 1.0200x; 1.0200x over previous
#include <cuda_runtime.h>
#include <math.h>

#define TS   64
#define BB   32
#define VV   32000
#define HH   1024
#define EMBD 512
#define G4   4096
#define HB   32768          // HH*BB
#define GPL  (G4 * BB)

typedef unsigned long long ull;

#if defined(__CUDA_ARCH__) && __CUDA_ARCH__ >= 900
#define PDL_SYNC() cudaGridDependencySynchronize()
#else
#define PDL_SYNC()
#endif

// ---------------- device scratch ----------------
__device__ float d_emb[(size_t)TS * EMBD * BB];   // [t][k][b]
__device__ float d_comb[2 * HB];
__device__ float d_h0p[HB];
__device__ float d_h1i[HB];
__device__ float d_c0p[HB], d_c1p[HB];
__device__ float d_g[4 * (size_t)GPL];            // 4 partial planes
__device__ float d_kp[8 * (size_t)HB];
__device__ float d_cp[8 * (size_t)HB];
__device__ float d_hbuf[(size_t)TS * HB];
__device__ float d_keys[(size_t)TS * HB];
__device__ float d_sc[TS * BB];
__device__ float d_dist[2 * TS * BB];
__device__ float d_sumv[HB];
__device__ float d_pexp[(size_t)VV * BB];
__device__ float d_red[500 * BB];
__device__ float d_ce[BB], d_f[BB], d_cw[BB];

// tile-major packed weights: tile(jt,kt) = 32k x 64j contiguous (2048 floats)
__device__ float dP_ih0[(size_t)1536 * G4];
__device__ float dP_hh0[(size_t)HH * G4];
__device__ float dP_ih1[(size_t)HH * G4];
__device__ float dP_hh1[(size_t)HH * G4];
__device__ float dP_k[(size_t)HH * HH];
__device__ float dP_c[(size_t)2048 * HH];
__device__ float dP_p[(size_t)HH * VV];

__device__ __forceinline__ float sigm(float x) { return 1.f / (1.f + expf(-x)); }

__device__ __forceinline__ void ffma2(ull& d, ull a, ull x) {
    asm("fma.rn.f32x2 %0, %1, %2, %0;" : "+l"(d) : "l"(a), "l"(x));
}
__device__ __forceinline__ ull pack2(float x) {
    ull r; unsigned int xi = __float_as_uint(x);
    asm("mov.b64 %0, {%1, %1};" : "=l"(r) : "r"(xi));
    return r;
}
__device__ __forceinline__ void unpack2(ull v, float& lo, float& hi) {
    unsigned int a, b;
    asm("mov.b64 {%0, %1}, %2;" : "=r"(a), "=r"(b) : "l"(v));
    lo = __uint_as_float(a); hi = __uint_as_float(b);
}
__device__ __forceinline__ unsigned smem_u32(const void* p) {
    return (unsigned)__cvta_generic_to_shared(p);
}
__device__ __forceinline__ void mbar_init(unsigned mba) {
    asm volatile("mbarrier.init.shared.b64 [%0], 1;" :: "r"(mba) : "memory");
}
__device__ __forceinline__ void mbar_expect(unsigned mba, unsigned bytes) {
    asm volatile("mbarrier.arrive.expect_tx.shared.b64 _, [%0], %1;"
                 :: "r"(mba), "r"(bytes) : "memory");
}
__device__ __forceinline__ void bulk_cp(unsigned sdst, const void* gsrc,
                                        unsigned bytes, unsigned mba) {
    asm volatile("cp.async.bulk.shared::cluster.global.mbarrier::complete_tx::bytes "
                 "[%0], [%1], %2, [%3];"
                 :: "r"(sdst), "l"(gsrc), "r"(bytes), "r"(mba) : "memory");
}
__device__ __forceinline__ void mwait(unsigned mba, int ph) {
    asm volatile(
        "{\n\t.reg .pred P;\n"
        "W%=:\n\t"
        "mbarrier.try_wait.parity.acquire.cta.shared::cta.b64 P, [%0], %1, 0x989680;\n\t"
        "@P bra D%=;\n\t"
        "bra W%=;\n"
        "D%=:\n\t}"
        :: "r"(mba), "r"(ph) : "memory");
}

// ---------------- repack: row-major [J][K] -> tile-major 32k x 64j ----------
struct TransTab { const float* s[7]; float* d[7]; int J[7]; int K[7]; };

__global__ void __launch_bounds__(256) k_trans(TransTab tt)
{
    __shared__ float sm[32][65];
    int id = blockIdx.x;
    int m = 0;
    for (;;) {
        int n = (tt.J[m] >> 6) * (tt.K[m] >> 5);
        if (id < n) break;
        id -= n; m++;
    }
    const float* src = tt.s[m];
    float* dst = tt.d[m];
    int J = tt.J[m], K = tt.K[m];
    int jtn = J >> 6;
    int jt = id % jtn, kt = id / jtn;
    int j0 = jt << 6, k0 = kt << 5;
    int tid = threadIdx.x;
#pragma unroll
    for (int i = 0; i < 2; i++) {
        int idx = tid + 256 * i;
        int jj = idx >> 3, q = (idx & 7) << 2;
        float4 v = *(const float4*)(src + (size_t)(j0 + jj) * K + k0 + q);
        sm[q + 0][jj] = v.x; sm[q + 1][jj] = v.y;
        sm[q + 2][jj] = v.z; sm[q + 3][jj] = v.w;
    }
    __syncthreads();
    float* base = dst + ((size_t)jt * (K >> 5) + kt) * 2048;
#pragma unroll
    for (int i = 0; i < 2; i++) {
        int idx = tid + 256 * i;
        int kk = idx >> 4, j4 = (idx & 15) << 2;
        *(float4*)(base + kk * 64 + j4) =
            make_float4(sm[kk][j4], sm[kk][j4 + 1], sm[kk][j4 + 2], sm[kk][j4 + 3]);
    }
}

// ---------------- GEMM: tile-major A, cp.async.bulk 3-stage mbarrier ring ----
__global__ void __launch_bounds__(256) k_gemm(
    const float* __restrict__ P0, const float* __restrict__ X0, int ldt0, int kto0, int t0,
    const float* __restrict__ P1, const float* __restrict__ X1, int ldt1, int kto1, int t1,
    const float* __restrict__ P2, const float* __restrict__ X2, int ldt2, int kto2, int t2,
    int tps, const float* __restrict__ bias1, const float* __restrict__ bias2,
    float* __restrict__ out, long long outPlane)
{
    __shared__ __align__(16) float As[3][2048];
    __shared__ __align__(16) float Xs[3][1024];
    __shared__ __align__(8)  ull  mbar[3];

    const int tid = threadIdx.x;
    const int b   = tid & 31, rg = tid >> 5;
    const int jt  = blockIdx.x;
    const int total = t0 + t1 + t2;
    const int g0 = blockIdx.y * tps;
    const int g1 = min(total, g0 + tps);

    const unsigned mb  = smem_u32(mbar);
    const unsigned sAs = smem_u32(As);
    const unsigned sXs = smem_u32(Xs);

    if (tid == 0) {
        mbar_init(mb); mbar_init(mb + 8); mbar_init(mb + 16);
        asm volatile("fence.proxy.async.shared::cta;" ::: "memory");
    }
    PDL_SYNC();
    __syncthreads();

    auto issue = [&](int g, int st) {
        const float* P; const float* X; int ldt, kto, lk;
        if (g < t0)           { P = P0; X = X0; ldt = ldt0; kto = kto0; lk = g; }
        else if (g < t0 + t1) { P = P1; X = X1; ldt = ldt1; kto = kto1; lk = g - t0; }
        else                  { P = P2; X = X2; ldt = ldt2; kto = kto2; lk = g - t0 - t1; }
        const float* a = P + ((size_t)jt * ldt + kto + lk) * 2048;
        const float* x = X + (size_t)lk * 1024;
        unsigned mba = mb + st * 8;
        mbar_expect(mba, 8192 + 4096);
        bulk_cp(sAs + st * 8192, a, 8192, mba);
        bulk_cp(sXs + st * 4096, x, 4096, mba);
    };

    if (tid == 0)
        for (int i = 0; i < 2 && g0 + i < g1; i++) issue(g0 + i, i);

    ull acc[4] = {0ull, 0ull, 0ull, 0ull};
    int st = 0, ph = 0;
    for (int g = g0; g < g1; g++) {
        mwait(mb + st * 8, ph);
        __syncthreads();
        if (tid == 0 && g + 2 < g1) {
            int rs = st + 2; if (rs >= 3) rs -= 3;
            issue(g + 2, rs);
        }
        const float* A_ = As[st];
        const float* X_ = Xs[st];
#pragma unroll
        for (int kk = 0; kk < 32; kk++) {
            ull xp = pack2(X_[kk * 32 + b]);
            const float* ab = A_ + kk * 64 + rg * 8;
            ulonglong2 u0 = *(const ulonglong2*)(ab);
            ulonglong2 u1 = *(const ulonglong2*)(ab + 4);
            ffma2(acc[0], u0.x, xp);
            ffma2(acc[1], u0.y, xp);
            ffma2(acc[2], u1.x, xp);
            ffma2(acc[3], u1.y, xp);
        }
        if (++st == 3) { st = 0; ph ^= 1; }
    }

    float* outp = out + blockIdx.y * outPlane;
#pragma unroll
    for (int p = 0; p < 4; p++) {
        float lo, hi;
        unpack2(acc[p], lo, hi);
        const int j = jt * 64 + rg * 8 + 2 * p;
        if (blockIdx.y == 0) {
            if (bias1) { lo += bias1[j]; hi += bias1[j + 1]; }
            if (bias2) { lo += bias2[j]; hi += bias2[j + 1]; }
        }
        outp[(size_t)j * BB + b]       = lo;
        outp[(size_t)(j + 1) * BB + b] = hi;
    }
}

// ---------------- logits: same pipeline + exp epilogue + block sum ----------
__global__ void __launch_bounds__(256) k_logits(
    const float* __restrict__ Pp, const float* __restrict__ comb,
    const float* __restrict__ bp, float* __restrict__ pexp, float* __restrict__ red)
{
    __shared__ __align__(16) float As[3][2048];
    __shared__ __align__(16) float Xs[3][1024];
    __shared__ __align__(8)  ull  mbar[3];
    __shared__ float sr[8][33];

    const int tid = threadIdx.x;
    const int b   = tid & 31, rg = tid >> 5;
    const int jt  = blockIdx.x;

    const unsigned mb  = smem_u32(mbar);
    const unsigned sAs = smem_u32(As);
    const unsigned sXs = smem_u32(Xs);

    if (tid == 0) {
        mbar_init(mb); mbar_init(mb + 8); mbar_init(mb + 16);
        asm volatile("fence.proxy.async.shared::cta;" ::: "memory");
    }
    PDL_SYNC();
    __syncthreads();

    auto issue = [&](int g, int st) {
        unsigned mba = mb + st * 8;
        mbar_expect(mba, 8192 + 4096);
        bulk_cp(sAs + st * 8192, Pp + ((size_t)jt * 32 + g) * 2048, 8192, mba);
        bulk_cp(sXs + st * 4096, comb + (size_t)g * 1024, 4096, mba);
    };

    if (tid == 0) { issue(0, 0); issue(1, 1); }

    ull acc[4] = {0ull, 0ull, 0ull, 0ull};
    int st = 0, ph = 0;
    for (int g = 0; g < 32; g++) {
        mwait(mb + st * 8, ph);
        __syncthreads();
        if (tid == 0 && g + 2 < 32) {
            int rs = st + 2; if (rs >= 3) rs -= 3;
            issue(g + 2, rs);
        }
        const float* A_ = As[st];
        const float* X_ = Xs[st];
#pragma unroll
        for (int kk = 0; kk < 32; kk++) {
            ull xp = pack2(X_[kk * 32 + b]);
            const float* ab = A_ + kk * 64 + rg * 8;
            ulonglong2 u0 = *(const ulonglong2*)(ab);
            ulonglong2 u1 = *(const ulonglong2*)(ab + 4);
            ffma2(acc[0], u0.x, xp);
            ffma2(acc[1], u0.y, xp);
            ffma2(acc[2], u1.x, xp);
            ffma2(acc[3], u1.y, xp);
        }
        if (++st == 3) { st = 0; ph ^= 1; }
    }

    float psum = 0.f;
#pragma unroll
    for (int p = 0; p < 4; p++) {
        float lo, hi; unpack2(acc[p], lo, hi);
        int j = jt * 64 + rg * 8 + 2 * p;
        float e0 = expf(lo + bp[j]);
        float e1 = expf(hi + bp[j + 1]);
        pexp[(size_t)j * BB + b]       = e0;
        pexp[(size_t)(j + 1) * BB + b] = e1;
        psum += e0 + e1;
    }
    sr[rg][b] = psum;
    __syncthreads();
    if (tid < 32) {
        float v = 0.f;
#pragma unroll
        for (int r = 0; r < 8; r++) v += sr[r][tid];
        red[jt * BB + tid] = v;
    }
}

// ---------------- small kernels ----------------
__global__ void k_embed_all(const float* __restrict__ E, const int* __restrict__ toks,
                            float* __restrict__ emb)
{
    int i = blockIdx.x * 256 + threadIdx.x;
    int b = i & 31, k = (i >> 5) & (EMBD - 1), t = i >> 14;
    emb[i] = E[(size_t)toks[t * BB + b] * EMBD + k];
}

__global__ void k_init(const float* __restrict__ h0, const float* __restrict__ c0,
                       float* h0p, float* h1i, float* c0p, float* c1p, float* comb)
{
    int i = blockIdx.x * 256 + threadIdx.x;
    int h = i >> 5, b = i & 31;
    h0p[i]  = h0[(size_t)b * HH + h];
    h1i[i]  = h0[(size_t)(BB + b) * HH + h];
    c0p[i]  = c0[(size_t)b * HH + h];
    c1p[i]  = c0[(size_t)(BB + b) * HH + h];
    comb[i] = 0.f;
    comb[HB + i] = 0.f;
}

__global__ void k_gates(const float* __restrict__ gp, float* __restrict__ c,
                        float* __restrict__ hout)
{
    PDL_SYNC();
    int i = blockIdx.x * 256 + threadIdx.x;
    float g[4];
#pragma unroll
    for (int m = 0; m < 4; m++) {
        size_t o = (size_t)m * HB + i;
        g[m] = gp[o] + gp[(size_t)GPL + o] + gp[2 * (size_t)GPL + o]
             + gp[3 * (size_t)GPL + o];
    }
    float c2 = sigm(g[1]) * c[i] + sigm(g[0]) * tanhf(g[2]);
    c[i] = c2;
    hout[i] = sigm(g[3]) * tanhf(c2);
}

__global__ void __launch_bounds__(256) k_scores(float* __restrict__ keys,
        const float* __restrict__ kp, const float* __restrict__ htop,
        const int* __restrict__ toks, float* __restrict__ sc, int t)
{
    PDL_SYNC();
    int s = blockIdx.x;
    int lane = threadIdx.x & 31, w = threadIdx.x >> 5;
    float acc = 0.f;
    if (s == t) {
        float* kf = keys + (size_t)t * HB;
        for (int h = w; h < HH; h += 8) {
            int i = h * BB + lane;
            float v = 0.f;
#pragma unroll
            for (int p = 0; p < 8; p++) v += kp[(size_t)p * HB + i];
            kf[i] = v;
            acc = fmaf(v, htop[i], acc);
        }
    } else {
        const float* ks = keys + (size_t)s * HB;
        for (int h = w; h < HH; h += 8)
            acc = fmaf(ks[h * BB + lane], htop[h * BB + lane], acc);
    }
    __shared__ float red[8][BB];
    red[w][lane] = acc;
    __syncthreads();
    if (w == 0) {
        float v = acc;
#pragma unroll
        for (int r = 1; r < 8; r++) v += red[r][lane];
        if (toks[s * BB + lane] == 0) v -= 99999.f;
        sc[s * BB + lane] = v;
    }
}

__global__ void k_summary(const float* __restrict__ sc, const float* __restrict__ hbuf,
                          int t, float* __restrict__ dist, float* __restrict__ sum)
{
    PDL_SYNC();
    __shared__ float sd[TS * BB];
    int tid = threadIdx.x;
    if (tid < 32) {
        int b = tid;
        float m = -1e30f;
        for (int s = 0; s <= t; s++) m = fmaxf(m, sc[s * BB + b]);
        float ss = 0.f;
        for (int s = 0; s <= t; s++) {
            float e = expf(sc[s * BB + b] - m);
            sd[s * BB + b] = e;
            ss += e;
        }
        float inv = 1.f / ss;
        for (int s = 0; s <= t; s++) {
            float dv = sd[s * BB + b] * inv;
            sd[s * BB + b] = dv;
            if (blockIdx.x == 0) dist[s * BB + b] = dv;
        }
    }
    __syncthreads();
    int gi = blockIdx.x * 256 + tid;
    int b = gi & 31;
    float acc = 0.f;
    for (int s = 0; s <= t; s++)
        acc = fmaf(sd[s * BB + b], hbuf[(size_t)s * HB + gi], acc);
    sum[gi] = acc;
}

__global__ void k_fincomb(const float* __restrict__ cp, float* __restrict__ comb)
{
    PDL_SYNC();
    int i = blockIdx.x * 256 + threadIdx.x;
    float v = 0.f;
#pragma unroll
    for (int p = 0; p < 8; p++) v += cp[(size_t)p * HB + i];
    comb[i] = v;
}

__global__ void k_reduce2(const float* __restrict__ red, const float* __restrict__ pexp,
                          float* __restrict__ ce, float* __restrict__ f,
                          float* __restrict__ cw)
{
    PDL_SYNC();
    int b = threadIdx.x;
    float S = 0.f;
    for (int i = 0; i < 500; i++) S += red[i * BB + b];
    float inv = 1.f / S;
    float c = pexp[3 * BB + b] * inv;
    ce[b] = c * 1e-7f;
    f[b]  = (1.f - c) * inv;
    cw[b] = c;
}

__global__ void __launch_bounds__(256) k_out(const float* __restrict__ pexp,
        const float* __restrict__ ce, const float* __restrict__ f,
        const float* __restrict__ cw, const int* __restrict__ toks,
        const float* __restrict__ dist, float* __restrict__ out, int t)
{
    PDL_SYNC();
    __shared__ float tile[128 * 33];
    int v0 = blockIdx.x * 128;
    int lane = threadIdx.x & 31, w = threadIdx.x >> 5;
    float ceL = ce[lane], fL = f[lane];
#pragma unroll
    for (int k = 0; k < 16; k++) {
        int vr = (k << 3) + w;
        tile[vr * 33 + lane] = logf(ceL + fL * pexp[(size_t)(v0 + vr) * BB + lane]);
    }
    __syncthreads();
    int bo = threadIdx.x >> 3, q = threadIdx.x & 7;
    float* op = out + (size_t)(t * BB + bo) * VV + v0;
#pragma unroll
    for (int i = 0; i < 4; i++) {
        int vb = (q + (i << 3)) << 2;
        *(float4*)(op + vb) = make_float4(tile[vb * 33 + bo],
                                          tile[(vb + 1) * 33 + bo],
                                          tile[(vb + 2) * 33 + bo],
                                          tile[(vb + 3) * 33 + bo]);
    }
    __syncthreads();
    float cwL = cw[lane];
    for (int s = w; s <= t; s += 8) {
        int v = toks[s * BB + lane];
        if (v >= v0 && v < v0 + 128) {
            bool first = true;
            for (int sp = 0; sp < s; sp++)
                if (toks[sp * BB + lane] == v) { first = false; break; }
            if (first) {
                float S = 0.f;
                for (int sp = s; sp <= t; sp++)
                    if (toks[sp * BB + lane] == v) S += dist[sp * BB + lane];
                out[(size_t)(t * BB + lane) * VV + v] =
                    logf(ceL + cwL * S + fL * pexp[(size_t)v * BB + lane]);
            }
        }
    }
}

// ---------------- host ----------------
static cudaLaunchAttribute g_at;
static cudaLaunchConfig_t mkcfg(dim3 gd, dim3 bd, cudaStream_t s)
{
    g_at.id = cudaLaunchAttributeProgrammaticStreamSerialization;
    g_at.val.programmaticStreamSerializationAllowed = 1;
    cudaLaunchConfig_t c = {};
    c.gridDim = gd; c.blockDim = bd; c.dynamicSmemBytes = 0;
    c.stream = s; c.attrs = &g_at; c.numAttrs = 1;
    return c;
}

extern "C" void kernel_launch(void* const* d_in, const int* in_sizes, int n_in,
                              void* d_out, int out_size)
{
    const int*   toks = (const int*)d_in[0];
    const float* h0   = (const float*)d_in[1];
    const float* c0   = (const float*)d_in[2];
    const float* E    = (const float*)d_in[3];
    const float* Wih0 = (const float*)d_in[4];
    const float* Whh0 = (const float*)d_in[5];
    const float* bih0 = (const float*)d_in[6];
    const float* bhh0 = (const float*)d_in[7];
    const float* Wih1 = (const float*)d_in[8];
    const float* Whh1 = (const float*)d_in[9];
    const float* bih1 = (const float*)d_in[10];
    const float* bhh1 = (const float*)d_in[11];
    const float* Wk   = (const float*)d_in[12];
    const float* bk   = (const float*)d_in[13];
    const float* Wc   = (const float*)d_in[14];
    const float* bc   = (const float*)d_in[15];
    const float* Wp   = (const float*)d_in[16];
    const float* bp   = (const float*)d_in[17];
    float* out = (float*)d_out;

    float *emb, *comb, *h0p, *h1i, *c0p, *c1p, *g, *kp, *cp, *hbuf, *keys;
    float *sc, *dist, *sumv, *pexp, *red, *ce, *f, *cw;
    float *Pih0, *Phh0, *Pih1, *Phh1, *Pk, *Pc, *Pp;
    cudaGetSymbolAddress((void**)&emb,  d_emb);
    cudaGetSymbolAddress((void**)&comb, d_comb);
    cudaGetSymbolAddress((void**)&h0p,  d_h0p);
    cudaGetSymbolAddress((void**)&h1i,  d_h1i);
    cudaGetSymbolAddress((void**)&c0p,  d_c0p);
    cudaGetSymbolAddress((void**)&c1p,  d_c1p);
    cudaGetSymbolAddress((void**)&g,    d_g);
    cudaGetSymbolAddress((void**)&kp,   d_kp);
    cudaGetSymbolAddress((void**)&cp,   d_cp);
    cudaGetSymbolAddress((void**)&hbuf, d_hbuf);
    cudaGetSymbolAddress((void**)&keys, d_keys);
    cudaGetSymbolAddress((void**)&sc,   d_sc);
    cudaGetSymbolAddress((void**)&dist, d_dist);
    cudaGetSymbolAddress((void**)&sumv, d_sumv);
    cudaGetSymbolAddress((void**)&pexp, d_pexp);
    cudaGetSymbolAddress((void**)&red,  d_red);
    cudaGetSymbolAddress((void**)&ce,   d_ce);
    cudaGetSymbolAddress((void**)&f,    d_f);
    cudaGetSymbolAddress((void**)&cw,   d_cw);
    cudaGetSymbolAddress((void**)&Pih0, dP_ih0);
    cudaGetSymbolAddress((void**)&Phh0, dP_hh0);
    cudaGetSymbolAddress((void**)&Pih1, dP_ih1);
    cudaGetSymbolAddress((void**)&Phh1, dP_hh1);
    cudaGetSymbolAddress((void**)&Pk,   dP_k);
    cudaGetSymbolAddress((void**)&Pc,   dP_c);
    cudaGetSymbolAddress((void**)&Pp,   dP_p);

    static cudaStream_t sA = nullptr;
    static cudaEvent_t evC[2], evD[2];
    if (!sA) {
        cudaStreamCreateWithFlags(&sA, cudaStreamNonBlocking);
        for (int i = 0; i < 2; i++) {
            cudaEventCreateWithFlags(&evC[i], cudaEventDisableTiming);
            cudaEventCreateWithFlags(&evD[i], cudaEventDisableTiming);
        }
    }

    k_embed_all<<<(TS * EMBD * BB) / 256, 256>>>(E, toks, emb);
    k_init<<<HB / 256, 256>>>(h0, c0, h0p, h1i, c0p, c1p, comb);

    TransTab tt;
    tt.s[0] = Wih0; tt.d[0] = Pih0; tt.J[0] = G4;   tt.K[0] = 1536;
    tt.s[1] = Whh0; tt.d[1] = Phh0; tt.J[1] = G4;   tt.K[1] = HH;
    tt.s[2] = Wih1; tt.d[2] = Pih1; tt.J[2] = G4;   tt.K[2] = HH;
    tt.s[3] = Whh1; tt.d[3] = Phh1; tt.J[3] = G4;   tt.K[3] = HH;
    tt.s[4] = Wk;   tt.d[4] = Pk;   tt.J[4] = HH;   tt.K[4] = HH;
    tt.s[5] = Wc;   tt.d[5] = Pc;   tt.J[5] = HH;   tt.K[5] = 2048;
    tt.s[6] = Wp;   tt.d[6] = Pp;   tt.J[6] = VV;   tt.K[6] = HH;
    int ntiles = 0;
    for (int m = 0; m < 7; m++) ntiles += (tt.J[m] >> 6) * (tt.K[m] >> 5);
    k_trans<<<ntiles, 256>>>(tt);

    const long long GPl = (long long)GPL;
    const float* FN = nullptr;

    for (int t = 0; t < TS; t++) {
        float* htop = hbuf + (size_t)t * HB;
        const float* h1prev   = t ? hbuf + (size_t)(t - 1) * HB : h1i;
        const float* emb_t    = emb + (size_t)t * EMBD * BB;
        const float* combPrev = comb + (size_t)((t + 1) & 1) * HB;
        float*       combCur  = comb + (size_t)(t & 1) * HB;
        float*       distCur  = dist + (size_t)(t & 1) * TS * BB;

        if (t >= 2) cudaStreamWaitEvent(0, evD[t & 1], 0);

        // LSTM0: 80 tiles (emb 16 | comb 32 | h0 32), ksplit 4 x 20
        {
            cudaLaunchConfig_t c = mkcfg(dim3(G4 / 64, 4), dim3(256), 0);
            cudaLaunchKernelEx(&c, k_gemm,
                Pih0, emb_t,    48, 0,  16,
                Pih0, combPrev, 48, 16, 32,
                Phh0, (const float*)h0p, 32, 0, 32,
                20, bih0, bhh0, g, GPl);
        }
        {
            cudaLaunchConfig_t c = mkcfg(dim3(HB / 256), dim3(256), 0);
            cudaLaunchKernelEx(&c, k_gates, (const float*)g, c0p, h0p);
        }

        // LSTM1: 64 tiles, ksplit 4 x 16
        {
            cudaLaunchConfig_t c = mkcfg(dim3(G4 / 64, 4), dim3(256), 0);
            cudaLaunchKernelEx(&c, k_gemm,
                (const float*)Pih1, (const float*)h0p, 32, 0, 32,
                (const float*)Phh1, h1prev, 32, 0, 32,
                FN, FN, 0, 0, 0,
                16, bih1, bhh1, g, GPl);
        }
        {
            cudaLaunchConfig_t c = mkcfg(dim3(HB / 256), dim3(256), 0);
            cudaLaunchKernelEx(&c, k_gates, (const float*)g, c1p, htop);
        }

        // keys[t]: 32 tiles, ksplit 8 x 4
        {
            cudaLaunchConfig_t c = mkcfg(dim3(HH / 64, 8), dim3(256), 0);
            cudaLaunchKernelEx(&c, k_gemm,
                (const float*)Pk, (const float*)htop, 32, 0, 32,
                FN, FN, 0, 0, 0,
                FN, FN, 0, 0, 0,
                4, bk, FN, kp, (long long)HB);
        }
        {
            cudaLaunchConfig_t c = mkcfg(dim3(t + 1), dim3(256), 0);
            cudaLaunchKernelEx(&c, k_scores, keys, (const float*)kp,
                               (const float*)htop, toks, sc, t);
        }
        {
            cudaLaunchConfig_t c = mkcfg(dim3(HB / 256), dim3(256), 0);
            cudaLaunchKernelEx(&c, k_summary, (const float*)sc,
                               (const float*)hbuf, t, distCur, sumv);
        }

        // comb: 64 tiles (htop 32 | sumv 32), ksplit 8 x 8
        {
            cudaLaunchConfig_t c = mkcfg(dim3(HH / 64, 8), dim3(256), 0);
            cudaLaunchKernelEx(&c, k_gemm,
                (const float*)Pc, (const float*)htop, 64, 0,  32,
                (const float*)Pc, (const float*)sumv, 64, 32, 32,
                FN, FN, 0, 0, 0,
                8, bc, FN, cp, (long long)HB);
        }
        {
            cudaLaunchConfig_t c = mkcfg(dim3(HB / 256), dim3(256), 0);
            cudaLaunchKernelEx(&c, k_fincomb, (const float*)cp, combCur);
        }
        cudaEventRecord(evC[t & 1], 0);

        // side chain (stream A)
        cudaStreamWaitEvent(sA, evC[t & 1], 0);
        {
            cudaLaunchConfig_t c = mkcfg(dim3(VV / 64), dim3(256), sA);
            cudaLaunchKernelEx(&c, k_logits, (const float*)Pp,
                               (const float*)combCur, bp, pexp, red);
        }
        {
            cudaLaunchConfig_t c = mkcfg(dim3(1), dim3(32), sA);
            cudaLaunchKernelEx(&c, k_reduce2, (const float*)red,
                               (const float*)pexp, ce, f, cw);
        }
        {
            cudaLaunchConfig_t c = mkcfg(dim3(VV / 128), dim3(256), sA);
            cudaLaunchKernelEx(&c, k_out, (const float*)pexp, (const float*)ce,
                               (const float*)f, (const float*)cw, toks,
                               (const float*)distCur, out, t);
        }
        cudaEventRecord(evD[t & 1], sA);
    }

    cudaStreamWaitEvent(0, evD[(TS - 1) & 1], 0);
    cudaStreamWaitEvent(0, evD[TS & 1], 0);
}